// round 16
// baseline (speedup 1.0000x reference)
#include <cuda_runtime.h>
#include <cuda_bf16.h>
#include <cstdint>

// Problem constants
#define B_   8
#define T_   4096
#define E_   1024
#define H_   16
#define L_   64
#define HD_  64
#define NBLK (T_ / L_)        // 64 blocks per sequence
#define M_   (B_ * T_)        // 32768 rows
#define N1_  (3 * E_)         // 3072

// Scratch (static device arrays: allowed; cudaMalloc is not)
__device__ float g_qkv[(size_t)M_ * N1_];                 // fp32 qkv (attention input)
__device__ __nv_bfloat16 g_xhi[(size_t)M_ * E_];
__device__ __nv_bfloat16 g_xlo[(size_t)M_ * E_];
__device__ __nv_bfloat16 g_ahi[(size_t)M_ * E_];
__device__ __nv_bfloat16 g_alo[(size_t)M_ * E_];
__device__ __nv_bfloat16 g_w1hi[(size_t)N1_ * E_];
__device__ __nv_bfloat16 g_w1lo[(size_t)N1_ * E_];
__device__ __nv_bfloat16 g_w2hi[(size_t)E_ * E_];
__device__ __nv_bfloat16 g_w2lo[(size_t)E_ * E_];

// ---------------------------------------------------------------------------
// Helpers
// ---------------------------------------------------------------------------
__device__ __forceinline__ uint32_t smem_u32(const void* p) {
    uint32_t a;
    asm("{ .reg .u64 t; cvta.to.shared.u64 t, %1; cvt.u32.u64 %0, t; }"
        : "=r"(a) : "l"(p));
    return a;
}

__device__ __forceinline__ void ldsm4(uint32_t* r, uint32_t addr) {
    asm volatile("ldmatrix.sync.aligned.m8n8.x4.shared.b16 {%0,%1,%2,%3}, [%4];"
                 : "=r"(r[0]), "=r"(r[1]), "=r"(r[2]), "=r"(r[3])
                 : "r"(addr));
}

__device__ __forceinline__ void mma16816(float* c, const uint32_t* a,
                                         const uint32_t* b) {
    asm volatile(
        "mma.sync.aligned.m16n8k16.row.col.f32.bf16.bf16.f32 "
        "{%0,%1,%2,%3}, {%4,%5,%6,%7}, {%8,%9}, {%0,%1,%2,%3};"
        : "+f"(c[0]), "+f"(c[1]), "+f"(c[2]), "+f"(c[3])
        : "r"(a[0]), "r"(a[1]), "r"(a[2]), "r"(a[3]),
          "r"(b[0]), "r"(b[1]));
}

__device__ __forceinline__ void cp16(uint32_t dst, const void* src) {
    asm volatile("cp.async.cg.shared.global [%0], [%1], 16;"
                 :: "r"(dst), "l"(src) : "memory");
}
#define CP_COMMIT() asm volatile("cp.async.commit_group;" ::: "memory")
#define CP_WAIT1()  asm volatile("cp.async.wait_group 1;" ::: "memory")

// Split 4 fp32 -> bf16 hi (uint2) + bf16 lo (uint2)
__device__ __forceinline__ void split4(const float* v, uint2& hw, uint2& lw) {
    __nv_bfloat162 h0 = __floats2bfloat162_rn(v[0], v[1]);
    __nv_bfloat162 h1 = __floats2bfloat162_rn(v[2], v[3]);
    float2 f0 = __bfloat1622float2(h0);
    float2 f1 = __bfloat1622float2(h1);
    __nv_bfloat162 l0 = __floats2bfloat162_rn(v[0] - f0.x, v[1] - f0.y);
    __nv_bfloat162 l1 = __floats2bfloat162_rn(v[2] - f1.x, v[3] - f1.y);
    hw.x = *reinterpret_cast<uint32_t*>(&h0);
    hw.y = *reinterpret_cast<uint32_t*>(&h1);
    lw.x = *reinterpret_cast<uint32_t*>(&l0);
    lw.y = *reinterpret_cast<uint32_t*>(&l1);
}

// Split 2 fp32 -> packed bf16x2 hi + lo
__device__ __forceinline__ void split2(float x, float y,
                                       uint32_t& hi, uint32_t& lo) {
    __nv_bfloat162 hb = __floats2bfloat162_rn(x, y);
    float2 f = __bfloat1622float2(hb);
    __nv_bfloat162 lb = __floats2bfloat162_rn(x - f.x, y - f.y);
    hi = *reinterpret_cast<uint32_t*>(&hb);
    lo = *reinterpret_cast<uint32_t*>(&lb);
}

// ---------------------------------------------------------------------------
// Elementwise fp32 -> bf16 hi/lo split
// ---------------------------------------------------------------------------
__global__ __launch_bounds__(256)
void split_fp32(const float4* __restrict__ src, uint2* __restrict__ hi,
                uint2* __restrict__ lo, int n4)
{
    int i = blockIdx.x * blockDim.x + threadIdx.x;
    if (i >= n4) return;
    float4 v = src[i];
    float a[4] = {v.x, v.y, v.z, v.w};
    uint2 hw, lw;
    split4(a, hw, lw);
    hi[i] = hw;
    lo[i] = lw;
}

// ---------------------------------------------------------------------------
// Split-bf16 tensor-core GEMM (unchanged from round 15; 82.5% tensor util)
// ---------------------------------------------------------------------------
#define GBM 128
#define GBN 128
#define GBK 32
#define SEG  8192
#define STAGE (4 * SEG)
#define NSTAGE 3
#define GEMM_SMEM (NSTAGE * STAGE)   // 98304

__device__ __forceinline__ uint32_t swz(uint32_t row, uint32_t chunk) {
    return row * 64 + ((chunk ^ ((row >> 1) & 3)) << 4);
}

__device__ __forceinline__ void load_chunk(
    uint32_t stageAddr, const __nv_bfloat16* aH, const __nv_bfloat16* aL,
    const __nv_bfloat16* bH, const __nv_bfloat16* bL,
    int tid, int K, int kOff)
{
#pragma unroll
    for (int i = 0; i < 2; i++) {
        int idx = tid + i * 256;
        uint32_t row = idx >> 2, ch = idx & 3;
        uint32_t off = swz(row, ch);
        long s = (long)row * K + kOff + ch * 8;
        cp16(stageAddr + off,           aH + s);
        cp16(stageAddr + SEG + off,     aL + s);
        cp16(stageAddr + 2 * SEG + off, bH + s);
        cp16(stageAddr + 3 * SEG + off, bL + s);
    }
}

__global__ __launch_bounds__(256, 2)
void gemm_tc(const __nv_bfloat16* __restrict__ Ahi,
             const __nv_bfloat16* __restrict__ Alo,
             const __nv_bfloat16* __restrict__ Bhi,
             const __nv_bfloat16* __restrict__ Blo,
             const float* __restrict__ bias, float* __restrict__ C,
             int N, int K)
{
    extern __shared__ char smem[];

    const int tid  = threadIdx.x;
    const int wid  = tid >> 5;
    const int lane = tid & 31;
    const int wm   = wid & 3;
    const int wn   = wid >> 2;

    const long mBase = (long)blockIdx.y * GBM;
    const long nBase = (long)blockIdx.x * GBN;
    const __nv_bfloat16* aH = Ahi + mBase * K;
    const __nv_bfloat16* aL = Alo + mBase * K;
    const __nv_bfloat16* bH = Bhi + nBase * K;
    const __nv_bfloat16* bL = Blo + nBase * K;

    float acc[2][8][4];
#pragma unroll
    for (int mt = 0; mt < 2; mt++)
#pragma unroll
        for (int nt = 0; nt < 8; nt++)
#pragma unroll
            for (int i = 0; i < 4; i++) acc[mt][nt][i] = 0.0f;

    const uint32_t aRow = (((lane >> 3) & 1) * 8) + (lane & 7);
    const uint32_t aKch = (lane >> 4);
    const uint32_t bRow = ((lane >> 4) * 8) + (lane & 7);
    const uint32_t bKch = ((lane >> 3) & 1);

    const uint32_t smemBase = smem_u32(smem);
    const int NC = K / GBK;

    load_chunk(smemBase,         aH, aL, bH, bL, tid, K, 0);
    CP_COMMIT();
    load_chunk(smemBase + STAGE, aH, aL, bH, bL, tid, K, GBK);
    CP_COMMIT();

    int stageIdx = 0;
    for (int c = 0; c < NC; c++) {
        CP_WAIT1();
        __syncthreads();

        const uint32_t stage = smemBase + stageIdx * STAGE;

#pragma unroll
        for (int ks = 0; ks < 2; ks++) {
            uint32_t ahi[2][4], alo[2][4];
#pragma unroll
            for (int mt = 0; mt < 2; mt++) {
                uint32_t row = wm * 32 + mt * 16 + aRow;
                uint32_t off = swz(row, ks * 2 + aKch);
                ldsm4(ahi[mt], stage + off);
                ldsm4(alo[mt], stage + SEG + off);
            }
#pragma unroll
            for (int np = 0; np < 4; np++) {
                uint32_t row = wn * 64 + np * 16 + bRow;
                uint32_t off = swz(row, ks * 2 + bKch);
                uint32_t bhi[4], blo[4];
                ldsm4(bhi, stage + 2 * SEG + off);
                ldsm4(blo, stage + 3 * SEG + off);
#pragma unroll
                for (int mt = 0; mt < 2; mt++)
#pragma unroll
                    for (int sub = 0; sub < 2; sub++) {
                        float* a4 = acc[mt][np * 2 + sub];
                        mma16816(a4, ahi[mt], &bhi[sub * 2]);
                        mma16816(a4, ahi[mt], &blo[sub * 2]);
                        mma16816(a4, alo[mt], &bhi[sub * 2]);
                    }
            }
        }

        if (c + 2 < NC) {
            int ns = stageIdx + 2;
            if (ns >= NSTAGE) ns -= NSTAGE;
            load_chunk(smemBase + ns * STAGE, aH, aL, bH, bL,
                       tid, K, (c + 2) * GBK);
        }
        CP_COMMIT();

        if (++stageIdx == NSTAGE) stageIdx = 0;
    }

    const int g  = lane >> 2;
    const int tg = lane & 3;
    const long wRow = mBase + wm * 32 + g;
    const long wCol = nBase + wn * 64 + tg * 2;

#pragma unroll
    for (int mt = 0; mt < 2; mt++) {
        long r0 = wRow + mt * 16;
#pragma unroll
        for (int nt = 0; nt < 8; nt++) {
            float2 bf = *(const float2*)(bias + wCol + nt * 8);
            float2 o0, o1;
            o0.x = acc[mt][nt][0] + bf.x;
            o0.y = acc[mt][nt][1] + bf.y;
            o1.x = acc[mt][nt][2] + bf.x;
            o1.y = acc[mt][nt][3] + bf.y;
            *(float2*)(C + r0 * N + wCol + nt * 8)       = o0;
            *(float2*)(C + (r0 + 8) * N + wCol + nt * 8) = o1;
        }
    }
}

// ---------------------------------------------------------------------------
// Local block attention on tensor cores (split-bf16, 3-pass).
// One CTA (128 threads, 4 warps) per (b,h,n) 64-token block.
// SMEM (dynamic, 72192 B): q/P hi,lo | k hi,lo | v^T hi,lo (bf16, pitch 144B)
//                          S (fp32, pitch 66 floats)
// ---------------------------------------------------------------------------
#define AP 144                     // bf16 tile pitch in bytes (72 elems)
#define SP 66                      // fp32 S pitch in floats
#define OFF_Q   0
#define OFF_QL  9216
#define OFF_K   18432
#define OFF_KL  27648
#define OFF_VT  36864
#define OFF_VTL 46080
#define OFF_S   55296
#define ATT_SMEM (OFF_S + L_ * SP * 4)   // 72192

// Warp-level 64x64x64 3-pass split-bf16 matmul: warp computes rows
// [w16, w16+16) of C; acc[8][4] covers n = 0..63 in n8 tiles.
__device__ __forceinline__ void warp_mma64(
    uint32_t aHi, uint32_t aLo, uint32_t bHi, uint32_t bLo,
    int w16, int lane, float acc[8][4])
{
#pragma unroll
    for (int nt = 0; nt < 8; nt++)
#pragma unroll
        for (int i = 0; i < 4; i++) acc[nt][i] = 0.0f;

    const uint32_t aRow = (((lane >> 3) & 1) * 8) + (lane & 7);
    const uint32_t aKch = (lane >> 4);
    const uint32_t bRow = ((lane >> 4) * 8) + (lane & 7);
    const uint32_t bKch = ((lane >> 3) & 1);

#pragma unroll
    for (int ks = 0; ks < 4; ks++) {
        uint32_t ah[4], al[4];
        uint32_t aOff = (w16 + aRow) * AP + (ks * 2 + aKch) * 16;
        ldsm4(ah, aHi + aOff);
        ldsm4(al, aLo + aOff);
#pragma unroll
        for (int np = 0; np < 4; np++) {
            uint32_t bOff = (np * 16 + bRow) * AP + (ks * 2 + bKch) * 16;
            uint32_t bh[4], bl[4];
            ldsm4(bh, bHi + bOff);
            ldsm4(bl, bLo + bOff);
#pragma unroll
            for (int sub = 0; sub < 2; sub++) {
                float* a4 = acc[np * 2 + sub];
                mma16816(a4, ah, &bh[sub * 2]);   // hi*hi
                mma16816(a4, ah, &bl[sub * 2]);   // hi*lo
                mma16816(a4, al, &bh[sub * 2]);   // lo*hi
            }
        }
    }
}

__global__ __launch_bounds__(128)
void local_attn(const float* __restrict__ qkv,
                __nv_bfloat16* __restrict__ outHi,
                __nv_bfloat16* __restrict__ outLo)
{
    extern __shared__ char sm[];
    float* bufS = (float*)(sm + OFF_S);

    const int bid = blockIdx.x;
    const int n = bid % NBLK;
    const int h = (bid / NBLK) % H_;
    const int b = bid / (NBLK * H_);
    const int tid  = threadIdx.x;
    const int wid  = tid >> 5;
    const int lane = tid & 31;
    const int w16  = wid * 16;

    const long rowBase = (long)b * T_ + (long)n * L_;
    const float scale = 0.125f;

    // ---- Load q (scaled), k, v^T; split to bf16 hi/lo in smem ----
    const int l    = tid >> 1;          // row 0..63
    const int c0   = (tid & 1) * 32;    // col half
    const float* qp = qkv + (rowBase + l) * (long)N1_ + h * HD_;

#pragma unroll
    for (int j = 0; j < 32; j += 4) {
        int c = c0 + j;
        float4 q4 = *(const float4*)(qp + c);
        float qa[4] = {q4.x * scale, q4.y * scale, q4.z * scale, q4.w * scale};
        uint2 hw, lw;
        split4(qa, hw, lw);
        *(uint2*)(sm + OFF_Q  + l * AP + c * 2) = hw;
        *(uint2*)(sm + OFF_QL + l * AP + c * 2) = lw;

        float4 k4 = *(const float4*)(qp + E_ + c);
        float ka[4] = {k4.x, k4.y, k4.z, k4.w};
        split4(ka, hw, lw);
        *(uint2*)(sm + OFF_K  + l * AP + c * 2) = hw;
        *(uint2*)(sm + OFF_KL + l * AP + c * 2) = lw;

        float4 v4 = *(const float4*)(qp + 2 * E_ + c);
        float va[4] = {v4.x, v4.y, v4.z, v4.w};
#pragma unroll
        for (int jj = 0; jj < 4; jj++) {
            __nv_bfloat16 hb = __float2bfloat16(va[jj]);
            __nv_bfloat16 lb = __float2bfloat16(va[jj] - __bfloat162float(hb));
            *(__nv_bfloat16*)(sm + OFF_VT  + (c + jj) * AP + l * 2) = hb;
            *(__nv_bfloat16*)(sm + OFF_VTL + (c + jj) * AP + l * 2) = lb;
        }
    }
    __syncthreads();

    const uint32_t base = smem_u32(sm);
    const int g  = lane >> 2;
    const int tg = lane & 3;

    // ---- S = q @ k^T (3-pass split bf16) ----
    float acc[8][4];
    warp_mma64(base + OFF_Q, base + OFF_QL, base + OFF_K, base + OFF_KL,
               w16, lane, acc);

    // Write S fragments to fp32 smem
    {
        float* s0 = bufS + (w16 + g) * SP;
        float* s1 = bufS + (w16 + g + 8) * SP;
#pragma unroll
        for (int np = 0; np < 8; np++) {
            int col = np * 8 + tg * 2;
            s0[col]     = acc[np][0];
            s0[col + 1] = acc[np][1];
            s1[col]     = acc[np][2];
            s1[col + 1] = acc[np][3];
        }
    }
    __syncthreads();

    // ---- Row softmax (warp shuffle), rows w16..w16+15 ----
#pragma unroll
    for (int rr = 0; rr < 16; rr++) {
        int r = w16 + rr;
        float v0 = bufS[r * SP + lane];
        float v1 = bufS[r * SP + lane + 32];
        float mx = fmaxf(v0, v1);
#pragma unroll
        for (int o = 16; o > 0; o >>= 1)
            mx = fmaxf(mx, __shfl_xor_sync(0xffffffffu, mx, o));
        float e0 = __expf(v0 - mx);
        float e1 = __expf(v1 - mx);
        float smv = e0 + e1;
#pragma unroll
        for (int o = 16; o > 0; o >>= 1)
            smv += __shfl_xor_sync(0xffffffffu, smv, o);
        float inv = 1.0f / smv;
        bufS[r * SP + lane]      = e0 * inv;
        bufS[r * SP + lane + 32] = e1 * inv;
    }
    __syncthreads();

    // ---- Split P into bf16 hi/lo (reuse q smem region) ----
#pragma unroll
    for (int j = 0; j < 32; j += 4) {
        int c = c0 + j;
        float pa[4] = {bufS[l * SP + c],     bufS[l * SP + c + 1],
                       bufS[l * SP + c + 2], bufS[l * SP + c + 3]};
        uint2 hw, lw;
        split4(pa, hw, lw);
        *(uint2*)(sm + OFF_Q  + l * AP + c * 2) = hw;
        *(uint2*)(sm + OFF_QL + l * AP + c * 2) = lw;
    }
    __syncthreads();

    // ---- O = P @ v (3-pass split bf16; B = v^T) ----
    warp_mma64(base + OFF_Q, base + OFF_QL, base + OFF_VT, base + OFF_VTL,
               w16, lane, acc);

    // ---- Write O split to gmem ----
    const long oCol = h * HD_ + tg * 2;
#pragma unroll
    for (int np = 0; np < 8; np++) {
        long r0 = (rowBase + w16 + g) * (long)E_ + oCol + np * 8;
        long r1 = (rowBase + w16 + g + 8) * (long)E_ + oCol + np * 8;
        uint32_t hi, lo;
        split2(acc[np][0], acc[np][1], hi, lo);
        *(uint32_t*)(outHi + r0) = hi;
        *(uint32_t*)(outLo + r0) = lo;
        split2(acc[np][2], acc[np][3], hi, lo);
        *(uint32_t*)(outHi + r1) = hi;
        *(uint32_t*)(outLo + r1) = lo;
    }
}

// ---------------------------------------------------------------------------
// Launch
// ---------------------------------------------------------------------------
extern "C" void kernel_launch(void* const* d_in, const int* in_sizes, int n_in,
                              void* d_out, int out_size)
{
    const float* x    = (const float*)d_in[0];
    const float* Wqkv = (const float*)d_in[1];
    const float* bqkv = (const float*)d_in[2];
    const float* Wout = (const float*)d_in[3];
    const float* bout = (const float*)d_in[4];
    float* out = (float*)d_out;

    void* p;
    cudaGetSymbolAddress(&p, g_qkv);  float* qkv = (float*)p;
    cudaGetSymbolAddress(&p, g_xhi);  __nv_bfloat16* xhi = (__nv_bfloat16*)p;
    cudaGetSymbolAddress(&p, g_xlo);  __nv_bfloat16* xlo = (__nv_bfloat16*)p;
    cudaGetSymbolAddress(&p, g_ahi);  __nv_bfloat16* ahi = (__nv_bfloat16*)p;
    cudaGetSymbolAddress(&p, g_alo);  __nv_bfloat16* alo = (__nv_bfloat16*)p;
    cudaGetSymbolAddress(&p, g_w1hi); __nv_bfloat16* w1hi = (__nv_bfloat16*)p;
    cudaGetSymbolAddress(&p, g_w1lo); __nv_bfloat16* w1lo = (__nv_bfloat16*)p;
    cudaGetSymbolAddress(&p, g_w2hi); __nv_bfloat16* w2hi = (__nv_bfloat16*)p;
    cudaGetSymbolAddress(&p, g_w2lo); __nv_bfloat16* w2lo = (__nv_bfloat16*)p;

    cudaFuncSetAttribute(gemm_tc, cudaFuncAttributeMaxDynamicSharedMemorySize,
                         GEMM_SMEM);
    cudaFuncSetAttribute(local_attn,
                         cudaFuncAttributeMaxDynamicSharedMemorySize, ATT_SMEM);

    // Split inputs to bf16 hi/lo
    {
        int n4 = M_ * E_ / 4;
        split_fp32<<<(n4 + 255) / 256, 256>>>((const float4*)x,
                                              (uint2*)xhi, (uint2*)xlo, n4);
        n4 = N1_ * E_ / 4;
        split_fp32<<<(n4 + 255) / 256, 256>>>((const float4*)Wqkv,
                                              (uint2*)w1hi, (uint2*)w1lo, n4);
        n4 = E_ * E_ / 4;
        split_fp32<<<(n4 + 255) / 256, 256>>>((const float4*)Wout,
                                              (uint2*)w2hi, (uint2*)w2lo, n4);
    }

    // GEMM1: qkv = x @ Wqkv^T + bqkv  (32768 x 3072 x 1024)
    gemm_tc<<<dim3(N1_ / GBN, M_ / GBM), 256, GEMM_SMEM>>>(
        xhi, xlo, w1hi, w1lo, bqkv, qkv, N1_, E_);

    // Local block attention (tensor cores) -> split bf16 output
    local_attn<<<B_ * H_ * NBLK, 128, ATT_SMEM>>>(qkv, ahi, alo);

    // GEMM2: out = att @ Wout^T + bout (32768 x 1024 x 1024)
    gemm_tc<<<dim3(E_ / GBN, M_ / GBM), 256, GEMM_SMEM>>>(
        ahi, alo, w2hi, w2lo, bout, out, E_, E_);
}

// round 17
// speedup vs baseline: 1.0946x; 1.0946x over previous
#include <cuda_runtime.h>
#include <cuda_bf16.h>
#include <cstdint>

// Problem constants
#define B_   8
#define T_   4096
#define E_   1024
#define H_   16
#define L_   64
#define HD_  64
#define NBLK (T_ / L_)        // 64 blocks per sequence
#define M_   (B_ * T_)        // 32768 rows
#define N1_  (3 * E_)         // 3072

// Scratch (static device arrays: allowed; cudaMalloc is not)
__device__ __nv_bfloat16 g_qkvhi[(size_t)M_ * N1_];   // qkv split hi
__device__ __nv_bfloat16 g_qkvlo[(size_t)M_ * N1_];   // qkv split lo
__device__ __nv_bfloat16 g_xhi[(size_t)M_ * E_];
__device__ __nv_bfloat16 g_xlo[(size_t)M_ * E_];
__device__ __nv_bfloat16 g_ahi[(size_t)M_ * E_];
__device__ __nv_bfloat16 g_alo[(size_t)M_ * E_];
__device__ __nv_bfloat16 g_w1hi[(size_t)N1_ * E_];
__device__ __nv_bfloat16 g_w1lo[(size_t)N1_ * E_];
__device__ __nv_bfloat16 g_w2hi[(size_t)E_ * E_];
__device__ __nv_bfloat16 g_w2lo[(size_t)E_ * E_];

// ---------------------------------------------------------------------------
// Helpers
// ---------------------------------------------------------------------------
__device__ __forceinline__ uint32_t smem_u32(const void* p) {
    uint32_t a;
    asm("{ .reg .u64 t; cvta.to.shared.u64 t, %1; cvt.u32.u64 %0, t; }"
        : "=r"(a) : "l"(p));
    return a;
}

__device__ __forceinline__ void ldsm4(uint32_t* r, uint32_t addr) {
    asm volatile("ldmatrix.sync.aligned.m8n8.x4.shared.b16 {%0,%1,%2,%3}, [%4];"
                 : "=r"(r[0]), "=r"(r[1]), "=r"(r[2]), "=r"(r[3])
                 : "r"(addr));
}

__device__ __forceinline__ void ldsm4t(uint32_t* r, uint32_t addr) {
    asm volatile("ldmatrix.sync.aligned.m8n8.x4.trans.shared.b16 {%0,%1,%2,%3}, [%4];"
                 : "=r"(r[0]), "=r"(r[1]), "=r"(r[2]), "=r"(r[3])
                 : "r"(addr));
}

__device__ __forceinline__ void mma16816(float* c, const uint32_t* a,
                                         const uint32_t* b) {
    asm volatile(
        "mma.sync.aligned.m16n8k16.row.col.f32.bf16.bf16.f32 "
        "{%0,%1,%2,%3}, {%4,%5,%6,%7}, {%8,%9}, {%0,%1,%2,%3};"
        : "+f"(c[0]), "+f"(c[1]), "+f"(c[2]), "+f"(c[3])
        : "r"(a[0]), "r"(a[1]), "r"(a[2]), "r"(a[3]),
          "r"(b[0]), "r"(b[1]));
}

__device__ __forceinline__ void cp16(uint32_t dst, const void* src) {
    asm volatile("cp.async.cg.shared.global [%0], [%1], 16;"
                 :: "r"(dst), "l"(src) : "memory");
}
#define CP_COMMIT() asm volatile("cp.async.commit_group;" ::: "memory")
#define CP_WAIT1()  asm volatile("cp.async.wait_group 1;" ::: "memory")
#define CP_WAIT0()  asm volatile("cp.async.wait_group 0;" ::: "memory")

// Split 4 fp32 -> bf16 hi (uint2) + bf16 lo (uint2)
__device__ __forceinline__ void split4(const float* v, uint2& hw, uint2& lw) {
    __nv_bfloat162 h0 = __floats2bfloat162_rn(v[0], v[1]);
    __nv_bfloat162 h1 = __floats2bfloat162_rn(v[2], v[3]);
    float2 f0 = __bfloat1622float2(h0);
    float2 f1 = __bfloat1622float2(h1);
    __nv_bfloat162 l0 = __floats2bfloat162_rn(v[0] - f0.x, v[1] - f0.y);
    __nv_bfloat162 l1 = __floats2bfloat162_rn(v[2] - f1.x, v[3] - f1.y);
    hw.x = *reinterpret_cast<uint32_t*>(&h0);
    hw.y = *reinterpret_cast<uint32_t*>(&h1);
    lw.x = *reinterpret_cast<uint32_t*>(&l0);
    lw.y = *reinterpret_cast<uint32_t*>(&l1);
}

// Split 2 fp32 -> packed bf16x2 hi + lo
__device__ __forceinline__ void split2(float x, float y,
                                       uint32_t& hi, uint32_t& lo) {
    __nv_bfloat162 hb = __floats2bfloat162_rn(x, y);
    float2 f = __bfloat1622float2(hb);
    __nv_bfloat162 lb = __floats2bfloat162_rn(x - f.x, y - f.y);
    hi = *reinterpret_cast<uint32_t*>(&hb);
    lo = *reinterpret_cast<uint32_t*>(&lb);
}

// ---------------------------------------------------------------------------
// Elementwise fp32 -> bf16 hi/lo split
// ---------------------------------------------------------------------------
__global__ __launch_bounds__(256)
void split_fp32(const float4* __restrict__ src, uint2* __restrict__ hi,
                uint2* __restrict__ lo, int n4)
{
    int i = blockIdx.x * blockDim.x + threadIdx.x;
    if (i >= n4) return;
    float4 v = src[i];
    float a[4] = {v.x, v.y, v.z, v.w};
    uint2 hw, lw;
    split4(a, hw, lw);
    hi[i] = hw;
    lo[i] = lw;
}

// ---------------------------------------------------------------------------
// Split-bf16 tensor-core GEMM (mainloop identical to round 15).
// Epilogue: fp32 (Cf) OR split bf16 hi/lo (Chi/Clo) when Chi != nullptr.
// ---------------------------------------------------------------------------
#define GBM 128
#define GBN 128
#define GBK 32
#define SEG  8192
#define STAGE (4 * SEG)
#define NSTAGE 3
#define GEMM_SMEM (NSTAGE * STAGE)   // 98304

__device__ __forceinline__ uint32_t swz(uint32_t row, uint32_t chunk) {
    return row * 64 + ((chunk ^ ((row >> 1) & 3)) << 4);
}

__device__ __forceinline__ void load_chunk(
    uint32_t stageAddr, const __nv_bfloat16* aH, const __nv_bfloat16* aL,
    const __nv_bfloat16* bH, const __nv_bfloat16* bL,
    int tid, int K, int kOff)
{
#pragma unroll
    for (int i = 0; i < 2; i++) {
        int idx = tid + i * 256;
        uint32_t row = idx >> 2, ch = idx & 3;
        uint32_t off = swz(row, ch);
        long s = (long)row * K + kOff + ch * 8;
        cp16(stageAddr + off,           aH + s);
        cp16(stageAddr + SEG + off,     aL + s);
        cp16(stageAddr + 2 * SEG + off, bH + s);
        cp16(stageAddr + 3 * SEG + off, bL + s);
    }
}

__global__ __launch_bounds__(256, 2)
void gemm_tc(const __nv_bfloat16* __restrict__ Ahi,
             const __nv_bfloat16* __restrict__ Alo,
             const __nv_bfloat16* __restrict__ Bhi,
             const __nv_bfloat16* __restrict__ Blo,
             const float* __restrict__ bias, float* __restrict__ Cf,
             __nv_bfloat16* __restrict__ Chi, __nv_bfloat16* __restrict__ Clo,
             int N, int K)
{
    extern __shared__ char smem[];

    const int tid  = threadIdx.x;
    const int wid  = tid >> 5;
    const int lane = tid & 31;
    const int wm   = wid & 3;
    const int wn   = wid >> 2;

    const long mBase = (long)blockIdx.y * GBM;
    const long nBase = (long)blockIdx.x * GBN;
    const __nv_bfloat16* aH = Ahi + mBase * K;
    const __nv_bfloat16* aL = Alo + mBase * K;
    const __nv_bfloat16* bH = Bhi + nBase * K;
    const __nv_bfloat16* bL = Blo + nBase * K;

    float acc[2][8][4];
#pragma unroll
    for (int mt = 0; mt < 2; mt++)
#pragma unroll
        for (int nt = 0; nt < 8; nt++)
#pragma unroll
            for (int i = 0; i < 4; i++) acc[mt][nt][i] = 0.0f;

    const uint32_t aRow = (((lane >> 3) & 1) * 8) + (lane & 7);
    const uint32_t aKch = (lane >> 4);
    const uint32_t bRow = ((lane >> 4) * 8) + (lane & 7);
    const uint32_t bKch = ((lane >> 3) & 1);

    const uint32_t smemBase = smem_u32(smem);
    const int NC = K / GBK;

    load_chunk(smemBase,         aH, aL, bH, bL, tid, K, 0);
    CP_COMMIT();
    load_chunk(smemBase + STAGE, aH, aL, bH, bL, tid, K, GBK);
    CP_COMMIT();

    int stageIdx = 0;
    for (int c = 0; c < NC; c++) {
        CP_WAIT1();
        __syncthreads();

        const uint32_t stage = smemBase + stageIdx * STAGE;

#pragma unroll
        for (int ks = 0; ks < 2; ks++) {
            uint32_t ahi[2][4], alo[2][4];
#pragma unroll
            for (int mt = 0; mt < 2; mt++) {
                uint32_t row = wm * 32 + mt * 16 + aRow;
                uint32_t off = swz(row, ks * 2 + aKch);
                ldsm4(ahi[mt], stage + off);
                ldsm4(alo[mt], stage + SEG + off);
            }
#pragma unroll
            for (int np = 0; np < 4; np++) {
                uint32_t row = wn * 64 + np * 16 + bRow;
                uint32_t off = swz(row, ks * 2 + bKch);
                uint32_t bhi[4], blo[4];
                ldsm4(bhi, stage + 2 * SEG + off);
                ldsm4(blo, stage + 3 * SEG + off);
#pragma unroll
                for (int mt = 0; mt < 2; mt++)
#pragma unroll
                    for (int sub = 0; sub < 2; sub++) {
                        float* a4 = acc[mt][np * 2 + sub];
                        mma16816(a4, ahi[mt], &bhi[sub * 2]);
                        mma16816(a4, ahi[mt], &blo[sub * 2]);
                        mma16816(a4, alo[mt], &bhi[sub * 2]);
                    }
            }
        }

        if (c + 2 < NC) {
            int ns = stageIdx + 2;
            if (ns >= NSTAGE) ns -= NSTAGE;
            load_chunk(smemBase + ns * STAGE, aH, aL, bH, bL,
                       tid, K, (c + 2) * GBK);
        }
        CP_COMMIT();

        if (++stageIdx == NSTAGE) stageIdx = 0;
    }

    const int g  = lane >> 2;
    const int tg = lane & 3;
    const long wRow = mBase + wm * 32 + g;
    const long wCol = nBase + wn * 64 + tg * 2;

    if (Chi) {
        // Split bf16 hi/lo epilogue
#pragma unroll
        for (int mt = 0; mt < 2; mt++) {
            long r0 = wRow + mt * 16;
#pragma unroll
            for (int nt = 0; nt < 8; nt++) {
                float2 bf = *(const float2*)(bias + wCol + nt * 8);
                long p0 = r0 * N + wCol + nt * 8;
                long p1 = (r0 + 8) * N + wCol + nt * 8;
                uint32_t hi, lo;
                split2(acc[mt][nt][0] + bf.x, acc[mt][nt][1] + bf.y, hi, lo);
                *(uint32_t*)(Chi + p0) = hi;
                *(uint32_t*)(Clo + p0) = lo;
                split2(acc[mt][nt][2] + bf.x, acc[mt][nt][3] + bf.y, hi, lo);
                *(uint32_t*)(Chi + p1) = hi;
                *(uint32_t*)(Clo + p1) = lo;
            }
        }
    } else {
        // fp32 epilogue
#pragma unroll
        for (int mt = 0; mt < 2; mt++) {
            long r0 = wRow + mt * 16;
#pragma unroll
            for (int nt = 0; nt < 8; nt++) {
                float2 bf = *(const float2*)(bias + wCol + nt * 8);
                float2 o0, o1;
                o0.x = acc[mt][nt][0] + bf.x;
                o0.y = acc[mt][nt][1] + bf.y;
                o1.x = acc[mt][nt][2] + bf.x;
                o1.y = acc[mt][nt][3] + bf.y;
                *(float2*)(Cf + r0 * N + wCol + nt * 8)       = o0;
                *(float2*)(Cf + (r0 + 8) * N + wCol + nt * 8) = o1;
            }
        }
    }
}

// ---------------------------------------------------------------------------
// Local block attention v3: split-bf16 tensor cores end-to-end.
// One CTA (128 threads, 4 warps) per (b,h,n) block.
// qkv arrives pre-split (hi/lo bf16 from GEMM1 epilogue); all 6 tiles loaded
// via cp.async. Softmax in registers (4-lane shuffles). P overwrites q tile
// (warp-private rows -> __syncwarp only). P@V uses ldmatrix.trans on
// row-major v. ONE __syncthreads total.
// Tile pitch 144B (9x16B granules/row: conflict-free ldmatrix, 16B-aligned).
// ---------------------------------------------------------------------------
#define ATP 144
#define AT  9216                      // 64 * 144
#define ATT_SMEM (6 * AT)             // 55296

// 3-pass split-bf16 64x64x64: warp computes rows [w16, w16+16).
// B non-transposed: B tile stored [n][k] row-major (k tile for S).
__device__ __forceinline__ void warp_mma64(
    uint32_t aHi, uint32_t aLo, uint32_t bHi, uint32_t bLo,
    int w16, int lane, float acc[8][4])
{
#pragma unroll
    for (int nt = 0; nt < 8; nt++)
#pragma unroll
        for (int i = 0; i < 4; i++) acc[nt][i] = 0.0f;

    const uint32_t aRow = (((lane >> 3) & 1) * 8) + (lane & 7);
    const uint32_t aKch = (lane >> 4);
    const uint32_t bRow = ((lane >> 4) * 8) + (lane & 7);
    const uint32_t bKch = ((lane >> 3) & 1);

#pragma unroll
    for (int ks = 0; ks < 4; ks++) {
        uint32_t ah[4], al[4];
        uint32_t aOff = (w16 + aRow) * ATP + (ks * 2 + aKch) * 16;
        ldsm4(ah, aHi + aOff);
        ldsm4(al, aLo + aOff);
#pragma unroll
        for (int np = 0; np < 4; np++) {
            uint32_t bOff = (np * 16 + bRow) * ATP + (ks * 2 + bKch) * 16;
            uint32_t bh[4], bl[4];
            ldsm4(bh, bHi + bOff);
            ldsm4(bl, bLo + bOff);
#pragma unroll
            for (int sub = 0; sub < 2; sub++) {
                float* a4 = acc[np * 2 + sub];
                mma16816(a4, ah, &bh[sub * 2]);
                mma16816(a4, ah, &bl[sub * 2]);
                mma16816(a4, al, &bh[sub * 2]);
            }
        }
    }
}

// Same but B comes from a row-major [k][n] tile via ldmatrix.trans (v tile).
__device__ __forceinline__ void warp_mma64_tb(
    uint32_t aHi, uint32_t aLo, uint32_t bHi, uint32_t bLo,
    int w16, int lane, float acc[8][4])
{
#pragma unroll
    for (int nt = 0; nt < 8; nt++)
#pragma unroll
        for (int i = 0; i < 4; i++) acc[nt][i] = 0.0f;

    const uint32_t aRow  = (((lane >> 3) & 1) * 8) + (lane & 7);
    const uint32_t aKch  = (lane >> 4);
    const uint32_t bRowT = (((lane >> 3) & 1) * 8) + (lane & 7);  // k (seq) row
    const uint32_t bNch  = (lane >> 4);                           // n 8-col half

#pragma unroll
    for (int ks = 0; ks < 4; ks++) {
        uint32_t ah[4], al[4];
        uint32_t aOff = (w16 + aRow) * ATP + (ks * 2 + aKch) * 16;
        ldsm4(ah, aHi + aOff);
        ldsm4(al, aLo + aOff);
#pragma unroll
        for (int np = 0; np < 4; np++) {
            uint32_t bOff = (ks * 16 + bRowT) * ATP + (np * 16 + bNch * 8) * 2;
            uint32_t bh[4], bl[4];
            ldsm4t(bh, bHi + bOff);
            ldsm4t(bl, bLo + bOff);
#pragma unroll
            for (int sub = 0; sub < 2; sub++) {
                float* a4 = acc[np * 2 + sub];
                mma16816(a4, ah, &bh[sub * 2]);
                mma16816(a4, ah, &bl[sub * 2]);
                mma16816(a4, al, &bh[sub * 2]);
            }
        }
    }
}

__global__ __launch_bounds__(128)
void local_attn(const __nv_bfloat16* __restrict__ qkvHi,
                const __nv_bfloat16* __restrict__ qkvLo,
                __nv_bfloat16* __restrict__ outHi,
                __nv_bfloat16* __restrict__ outLo)
{
    extern __shared__ char sm[];

    const int bid = blockIdx.x;
    const int n = bid % NBLK;
    const int h = (bid / NBLK) % H_;
    const int b = bid / (NBLK * H_);
    const int tid  = threadIdx.x;
    const int wid  = tid >> 5;
    const int lane = tid & 31;
    const int w16  = wid * 16;
    const long rowBase = (long)b * T_ + (long)n * L_;
    const float scale = 0.125f;

    const uint32_t base = smem_u32(sm);

    // ---- cp.async all six tiles (q/k/v x hi/lo), 24 LDGSTS per thread ----
    {
        const int trow = tid >> 1;
        const int tcol = (tid & 1) * 32;
        const long gbase = (rowBase + trow) * (long)N1_ + h * HD_ + tcol;
        const uint32_t drow = trow * ATP + tcol * 2;
#pragma unroll
        for (int part = 0; part < 2; part++) {
            const __nv_bfloat16* src = part ? qkvLo : qkvHi;
#pragma unroll
            for (int pc = 0; pc < 3; pc++) {       // 0=q, 1=k, 2=v
                uint32_t dst = base + (pc * 2 + part) * AT + drow;
                const __nv_bfloat16* s = src + gbase + pc * E_;
#pragma unroll
                for (int c = 0; c < 4; c++)
                    cp16(dst + c * 16, s + c * 8);
            }
        }
    }
    CP_COMMIT();
    CP_WAIT0();
    __syncthreads();        // the only CTA-wide barrier

    const uint32_t QH = base, QL = base + AT;
    const uint32_t KH = base + 2 * AT, KL = base + 3 * AT;
    const uint32_t VH = base + 4 * AT, VL = base + 5 * AT;

    // ---- S = q @ k^T (raw, unscaled) ----
    float acc[8][4];
    warp_mma64(QH, QL, KH, KL, w16, lane, acc);

    // ---- Softmax in registers; rows g and g+8 per thread ----
    {
        float m0 = -1e30f, m1 = -1e30f;
#pragma unroll
        for (int nt = 0; nt < 8; nt++) {
            m0 = fmaxf(m0, fmaxf(acc[nt][0], acc[nt][1]));
            m1 = fmaxf(m1, fmaxf(acc[nt][2], acc[nt][3]));
        }
        m0 = fmaxf(m0, __shfl_xor_sync(0xffffffffu, m0, 1));
        m0 = fmaxf(m0, __shfl_xor_sync(0xffffffffu, m0, 2));
        m1 = fmaxf(m1, __shfl_xor_sync(0xffffffffu, m1, 1));
        m1 = fmaxf(m1, __shfl_xor_sync(0xffffffffu, m1, 2));

        float s0 = 0.0f, s1 = 0.0f;
#pragma unroll
        for (int nt = 0; nt < 8; nt++) {
            acc[nt][0] = __expf((acc[nt][0] - m0) * scale);
            acc[nt][1] = __expf((acc[nt][1] - m0) * scale);
            acc[nt][2] = __expf((acc[nt][2] - m1) * scale);
            acc[nt][3] = __expf((acc[nt][3] - m1) * scale);
            s0 += acc[nt][0] + acc[nt][1];
            s1 += acc[nt][2] + acc[nt][3];
        }
        s0 += __shfl_xor_sync(0xffffffffu, s0, 1);
        s0 += __shfl_xor_sync(0xffffffffu, s0, 2);
        s1 += __shfl_xor_sync(0xffffffffu, s1, 1);
        s1 += __shfl_xor_sync(0xffffffffu, s1, 2);
        float i0 = 1.0f / s0, i1 = 1.0f / s1;
#pragma unroll
        for (int nt = 0; nt < 8; nt++) {
            acc[nt][0] *= i0; acc[nt][1] *= i0;
            acc[nt][2] *= i1; acc[nt][3] *= i1;
        }
    }

    // ---- Write P (hi/lo) over the dead q tile; rows are warp-private ----
    {
        const int g  = lane >> 2;
        const int tg = lane & 3;
        uint32_t r0off = (w16 + g) * ATP;
        uint32_t r1off = (w16 + g + 8) * ATP;
#pragma unroll
        for (int nt = 0; nt < 8; nt++) {
            uint32_t coff = (nt * 8 + tg * 2) * 2;
            uint32_t hi, lo;
            split2(acc[nt][0], acc[nt][1], hi, lo);
            *(uint32_t*)(sm + (r0off + coff))      = hi;
            *(uint32_t*)(sm + AT + (r0off + coff)) = lo;
            split2(acc[nt][2], acc[nt][3], hi, lo);
            *(uint32_t*)(sm + (r1off + coff))      = hi;
            *(uint32_t*)(sm + AT + (r1off + coff)) = lo;
        }
    }
    __syncwarp();

    // ---- O = P @ v (v row-major, B via ldmatrix.trans) ----
    warp_mma64_tb(QH, QL, VH, VL, w16, lane, acc);

    // ---- Store O split hi/lo ----
    {
        const int g  = lane >> 2;
        const int tg = lane & 3;
        const long r0 = rowBase + w16 + g;
        const long r1 = r0 + 8;
        const long colB = h * HD_ + tg * 2;
#pragma unroll
        for (int nt = 0; nt < 8; nt++) {
            long p0 = r0 * (long)E_ + colB + nt * 8;
            long p1 = r1 * (long)E_ + colB + nt * 8;
            uint32_t hi, lo;
            split2(acc[nt][0], acc[nt][1], hi, lo);
            *(uint32_t*)(outHi + p0) = hi;
            *(uint32_t*)(outLo + p0) = lo;
            split2(acc[nt][2], acc[nt][3], hi, lo);
            *(uint32_t*)(outHi + p1) = hi;
            *(uint32_t*)(outLo + p1) = lo;
        }
    }
}

// ---------------------------------------------------------------------------
// Launch
// ---------------------------------------------------------------------------
extern "C" void kernel_launch(void* const* d_in, const int* in_sizes, int n_in,
                              void* d_out, int out_size)
{
    const float* x    = (const float*)d_in[0];
    const float* Wqkv = (const float*)d_in[1];
    const float* bqkv = (const float*)d_in[2];
    const float* Wout = (const float*)d_in[3];
    const float* bout = (const float*)d_in[4];
    float* out = (float*)d_out;

    void* p;
    cudaGetSymbolAddress(&p, g_qkvhi); __nv_bfloat16* qh = (__nv_bfloat16*)p;
    cudaGetSymbolAddress(&p, g_qkvlo); __nv_bfloat16* ql = (__nv_bfloat16*)p;
    cudaGetSymbolAddress(&p, g_xhi);   __nv_bfloat16* xhi = (__nv_bfloat16*)p;
    cudaGetSymbolAddress(&p, g_xlo);   __nv_bfloat16* xlo = (__nv_bfloat16*)p;
    cudaGetSymbolAddress(&p, g_ahi);   __nv_bfloat16* ahi = (__nv_bfloat16*)p;
    cudaGetSymbolAddress(&p, g_alo);   __nv_bfloat16* alo = (__nv_bfloat16*)p;
    cudaGetSymbolAddress(&p, g_w1hi);  __nv_bfloat16* w1hi = (__nv_bfloat16*)p;
    cudaGetSymbolAddress(&p, g_w1lo);  __nv_bfloat16* w1lo = (__nv_bfloat16*)p;
    cudaGetSymbolAddress(&p, g_w2hi);  __nv_bfloat16* w2hi = (__nv_bfloat16*)p;
    cudaGetSymbolAddress(&p, g_w2lo);  __nv_bfloat16* w2lo = (__nv_bfloat16*)p;

    cudaFuncSetAttribute(gemm_tc, cudaFuncAttributeMaxDynamicSharedMemorySize,
                         GEMM_SMEM);
    cudaFuncSetAttribute(local_attn,
                         cudaFuncAttributeMaxDynamicSharedMemorySize, ATT_SMEM);

    // Split inputs to bf16 hi/lo
    {
        int n4 = M_ * E_ / 4;
        split_fp32<<<(n4 + 255) / 256, 256>>>((const float4*)x,
                                              (uint2*)xhi, (uint2*)xlo, n4);
        n4 = N1_ * E_ / 4;
        split_fp32<<<(n4 + 255) / 256, 256>>>((const float4*)Wqkv,
                                              (uint2*)w1hi, (uint2*)w1lo, n4);
        n4 = E_ * E_ / 4;
        split_fp32<<<(n4 + 255) / 256, 256>>>((const float4*)Wout,
                                              (uint2*)w2hi, (uint2*)w2lo, n4);
    }

    // GEMM1: qkv = x @ Wqkv^T + bqkv -> split hi/lo output
    gemm_tc<<<dim3(N1_ / GBN, M_ / GBM), 256, GEMM_SMEM>>>(
        xhi, xlo, w1hi, w1lo, bqkv, nullptr, qh, ql, N1_, E_);

    // Local block attention (tensor cores, 1 barrier) -> split bf16 output
    local_attn<<<B_ * H_ * NBLK, 128, ATT_SMEM>>>(qh, ql, ahi, alo);

    // GEMM2: out = att @ Wout^T + bout (fp32 output)
    gemm_tc<<<dim3(E_ / GBN, M_ / GBM), 256, GEMM_SMEM>>>(
        ahi, alo, w2hi, w2lo, bout, out, nullptr, nullptr, E_, E_);
}